// round 1
// baseline (speedup 1.0000x reference)
#include <cuda_runtime.h>
#include <math.h>

#define BATCH 4
#define T 4096
#define C 768
#define H 64
#define M_TOT (BATCH * T)
#define NSPLIT 4
#define BQ 128
#define BK 64

// Scratch (static device globals: allowed; runtime allocation is not)
__device__ float g_Q[M_TOT * H];
__device__ float g_K[M_TOT * H];
__device__ float g_V[M_TOT * H];
__device__ float g_m[M_TOT * NSPLIT];
__device__ float g_l[M_TOT * NSPLIT];
__device__ float g_acc[(size_t)M_TOT * NSPLIT * H];

// ---------------------------------------------------------------------------
// Kernel 1: fused QKV projection.  out[m][h] = sum_c x[m][c] * W[c][h]
// grid = (M_TOT/64, 3), block = 256.  Each block computes a 64x64 tile.
// ---------------------------------------------------------------------------
__global__ __launch_bounds__(256) void qkv_kernel(
    const float* __restrict__ x,
    const float* __restrict__ Wq,
    const float* __restrict__ Wk,
    const float* __restrict__ Wv)
{
    const float* W = (blockIdx.y == 0) ? Wq : (blockIdx.y == 1) ? Wk : Wv;
    float* out     = (blockIdx.y == 0) ? g_Q : (blockIdx.y == 1) ? g_K : g_V;

    __shared__ float Xs[64][36];   // padded stride 36: conflict-free, 16B-aligned
    __shared__ float Ws[32][64];

    const int m0 = blockIdx.x * 64;
    const int tx = threadIdx.x % 16;
    const int ty = threadIdx.x / 16;

    float acc[4][4];
#pragma unroll
    for (int i = 0; i < 4; i++)
#pragma unroll
        for (int j = 0; j < 4; j++) acc[i][j] = 0.0f;

    for (int k0 = 0; k0 < C; k0 += 32) {
        // Load X tile: 64 rows x 32 cols = 512 float4
#pragma unroll
        for (int i = 0; i < 2; i++) {
            int f = threadIdx.x + i * 256;          // 0..511
            int r = f >> 3, c4 = f & 7;
            float4 v = *(const float4*)&x[(size_t)(m0 + r) * C + k0 + c4 * 4];
            *(float4*)&Xs[r][c4 * 4] = v;
        }
        // Load W tile: 32 rows x 64 cols = 512 float4
#pragma unroll
        for (int i = 0; i < 2; i++) {
            int f = threadIdx.x + i * 256;
            int r = f >> 4, c4 = f & 15;
            float4 v = *(const float4*)&W[(size_t)(k0 + r) * H + c4 * 4];
            *(float4*)&Ws[r][c4 * 4] = v;
        }
        __syncthreads();

#pragma unroll
        for (int kk = 0; kk < 32; kk++) {
            float a0 = Xs[ty * 4 + 0][kk];
            float a1 = Xs[ty * 4 + 1][kk];
            float a2 = Xs[ty * 4 + 2][kk];
            float a3 = Xs[ty * 4 + 3][kk];
            float4 b4 = *(const float4*)&Ws[kk][tx * 4];
            acc[0][0] += a0 * b4.x; acc[0][1] += a0 * b4.y; acc[0][2] += a0 * b4.z; acc[0][3] += a0 * b4.w;
            acc[1][0] += a1 * b4.x; acc[1][1] += a1 * b4.y; acc[1][2] += a1 * b4.z; acc[1][3] += a1 * b4.w;
            acc[2][0] += a2 * b4.x; acc[2][1] += a2 * b4.y; acc[2][2] += a2 * b4.z; acc[2][3] += a2 * b4.w;
            acc[3][0] += a3 * b4.x; acc[3][1] += a3 * b4.y; acc[3][2] += a3 * b4.z; acc[3][3] += a3 * b4.w;
        }
        __syncthreads();
    }

#pragma unroll
    for (int i = 0; i < 4; i++) {
        float4 o = make_float4(acc[i][0], acc[i][1], acc[i][2], acc[i][3]);
        *(float4*)&out[(size_t)(m0 + ty * 4 + i) * H + tx * 4] = o;
    }
}

// ---------------------------------------------------------------------------
// Kernel 2: split-K causal flash attention (partials).
// grid = (T/BQ, NSPLIT, BATCH), block = BQ threads. 1 thread = 1 query.
// ---------------------------------------------------------------------------
__global__ __launch_bounds__(128) void flash_kernel()
{
    __shared__ float Ks[BK][H];
    __shared__ float Vs[BK][H];

    const int b     = blockIdx.z;
    const int split = blockIdx.y;
    const int qt    = blockIdx.x;
    const int q     = qt * BQ + threadIdx.x;       // query index within batch
    const int q_max = qt * BQ + BQ - 1;

    const int seg_begin = split * (T / NSPLIT);
    const int seg_end   = min(seg_begin + T / NSPLIT, q_max + 1);

    const size_t pbase = (size_t)(b * T + q) * NSPLIT + split;

    if (seg_begin >= seg_end) {
        g_m[pbase] = -INFINITY;
        g_l[pbase] = 0.0f;
        return;
    }

    // Load this thread's query row into registers
    float qreg[H];
    {
        const float4* Qp = (const float4*)(g_Q + (size_t)(b * T + q) * H);
#pragma unroll
        for (int i = 0; i < H / 4; i++) {
            float4 v = Qp[i];
            qreg[4 * i + 0] = v.x; qreg[4 * i + 1] = v.y;
            qreg[4 * i + 2] = v.z; qreg[4 * i + 3] = v.w;
        }
    }

    float acc[H];
#pragma unroll
    for (int d = 0; d < H; d++) acc[d] = 0.0f;
    float m = -INFINITY;
    float l = 0.0f;
    const float scale = 0.125f;   // 1/sqrt(64)

    for (int kt = seg_begin; kt < seg_end; kt += BK) {
        // Cooperative stage of K,V tiles (coalesced float4)
        const float4* Kp = (const float4*)(g_K + (size_t)(b * T + kt) * H);
        const float4* Vp = (const float4*)(g_V + (size_t)(b * T + kt) * H);
#pragma unroll
        for (int i = 0; i < 8; i++) {
            int f = threadIdx.x + i * 128;   // 0..1023 (BK*H/4)
            ((float4*)Ks)[f] = Kp[f];
            ((float4*)Vs)[f] = Vp[f];
        }
        __syncthreads();

#pragma unroll 1
        for (int jc = 0; jc < BK; jc += 16) {
            float s[16];
#pragma unroll
            for (int j = 0; j < 16; j++) {
                const float* kr = &Ks[jc + j][0];
                float sum0 = 0.0f, sum1 = 0.0f;
#pragma unroll
                for (int d = 0; d < H; d += 8) {
                    float4 ka = *(const float4*)(kr + d);
                    float4 kb = *(const float4*)(kr + d + 4);
                    sum0 += qreg[d + 0] * ka.x + qreg[d + 1] * ka.y
                          + qreg[d + 2] * ka.z + qreg[d + 3] * ka.w;
                    sum1 += qreg[d + 4] * kb.x + qreg[d + 5] * kb.y
                          + qreg[d + 6] * kb.z + qreg[d + 7] * kb.w;
                }
                int key = kt + jc + j;
                s[j] = (key <= q) ? (sum0 + sum1) * scale : -INFINITY;
            }

            float mc = s[0];
#pragma unroll
            for (int j = 1; j < 16; j++) mc = fmaxf(mc, s[j]);

            if (mc != -INFINITY) {            // skip fully-masked chunks (avoids NaN)
                float mnew  = fmaxf(m, mc);   // finite
                float alpha = __expf(m - mnew);  // m=-inf -> 0
                l *= alpha;
#pragma unroll
                for (int d = 0; d < H; d++) acc[d] *= alpha;
#pragma unroll
                for (int j = 0; j < 16; j++) {
                    float p = __expf(s[j] - mnew);   // masked -> exp(-inf)=0
                    l += p;
                    const float* vr = &Vs[jc + j][0];
#pragma unroll
                    for (int d = 0; d < H; d += 4) {
                        float4 v4 = *(const float4*)(vr + d);
                        acc[d + 0] += p * v4.x; acc[d + 1] += p * v4.y;
                        acc[d + 2] += p * v4.z; acc[d + 3] += p * v4.w;
                    }
                }
                m = mnew;
            }
        }
        __syncthreads();
    }

    // Store unnormalized partials
    g_m[pbase] = m;
    g_l[pbase] = l;
    float4* ap = (float4*)(g_acc + pbase * H);
#pragma unroll
    for (int i = 0; i < H / 4; i++) {
        ap[i] = make_float4(acc[4 * i + 0], acc[4 * i + 1],
                            acc[4 * i + 2], acc[4 * i + 3]);
    }
}

// ---------------------------------------------------------------------------
// Kernel 3: combine split-K partials.  1 thread per (query, dim).
// ---------------------------------------------------------------------------
__global__ __launch_bounds__(256) void combine_kernel(float* __restrict__ out)
{
    int idx   = blockIdx.x * 256 + threadIdx.x;    // 0 .. M_TOT*H-1
    int d     = idx & (H - 1);
    int query = idx >> 6;

    float mv[NSPLIT];
    float M = -INFINITY;
#pragma unroll
    for (int i = 0; i < NSPLIT; i++) {
        mv[i] = g_m[query * NSPLIT + i];
        M = fmaxf(M, mv[i]);
    }

    float L = 0.0f, o = 0.0f;
#pragma unroll
    for (int i = 0; i < NSPLIT; i++) {
        if (mv[i] != -INFINITY) {
            float w = __expf(mv[i] - M);
            L += g_l[query * NSPLIT + i] * w;
            o += g_acc[((size_t)query * NSPLIT + i) * H + d] * w;
        }
    }
    out[idx] = o / L;
}

// ---------------------------------------------------------------------------
extern "C" void kernel_launch(void* const* d_in, const int* in_sizes, int n_in,
                              void* d_out, int out_size)
{
    const float* x  = (const float*)d_in[0];
    const float* Wq = (const float*)d_in[1];
    const float* Wk = (const float*)d_in[2];
    const float* Wv = (const float*)d_in[3];
    float* out = (float*)d_out;

    qkv_kernel<<<dim3(M_TOT / 64, 3), 256>>>(x, Wq, Wk, Wv);
    flash_kernel<<<dim3(T / BQ, NSPLIT, BATCH), 128>>>();
    combine_kernel<<<(M_TOT * H) / 256, 256>>>(out);
}

// round 3
// speedup vs baseline: 3.2619x; 3.2619x over previous
#include <cuda_runtime.h>
#include <cuda_bf16.h>
#include <math.h>
#include <stdint.h>

#define BATCH 4
#define T 4096
#define C 768
#define H 64
#define M_TOT (BATCH * T)
#define NSPLIT 4

// Scratch (static device globals: allowed; runtime allocation is not)
__device__ float g_Q[M_TOT * H];
__device__ float g_K[M_TOT * H];
__device__ float g_V[M_TOT * H];
__device__ float g_m[M_TOT * NSPLIT];
__device__ float g_l[M_TOT * NSPLIT];
__device__ float g_acc[(size_t)M_TOT * NSPLIT * H];

// ============================================================================
// Warp-MMA primitives (sm_80+ portable; execute on tensor pipe as HMMA)
// ============================================================================
__device__ __forceinline__ uint32_t smem_to_u32(const void* smem_ptr) {
    uint32_t addr;
    asm("{ .reg .u64 tmp; cvta.to.shared.u64 tmp, %1; cvt.u32.u64 %0, tmp; }"
        : "=r"(addr) : "l"(smem_ptr));
    return addr;
}

// D(16x8,f32) += A(16x16,bf16) * B(16x8,bf16)
__device__ __forceinline__ void mma16816(float* d, const uint32_t* a, const uint32_t* b) {
    asm volatile(
        "mma.sync.aligned.m16n8k16.row.col.f32.bf16.bf16.f32 "
        "{%0,%1,%2,%3}, {%4,%5,%6,%7}, {%8,%9}, {%0,%1,%2,%3};"
        : "+f"(d[0]), "+f"(d[1]), "+f"(d[2]), "+f"(d[3])
        : "r"(a[0]), "r"(a[1]), "r"(a[2]), "r"(a[3]), "r"(b[0]), "r"(b[1]));
}

__device__ __forceinline__ void ldsm_x4(uint32_t* r, uint32_t a) {
    asm volatile("ldmatrix.sync.aligned.m8n8.x4.shared.b16 {%0,%1,%2,%3}, [%4];"
        : "=r"(r[0]), "=r"(r[1]), "=r"(r[2]), "=r"(r[3]) : "r"(a));
}

__device__ __forceinline__ void ldsm_x4_t(uint32_t* r, uint32_t a) {
    asm volatile("ldmatrix.sync.aligned.m8n8.x4.trans.shared.b16 {%0,%1,%2,%3}, [%4];"
        : "=r"(r[0]), "=r"(r[1]), "=r"(r[2]), "=r"(r[3]) : "r"(a));
}

// fp32 pair -> bf16x2 hi + bf16x2 residual(lo)
__device__ __forceinline__ void cvt_hilo(float vx, float vy, uint32_t& hi, uint32_t& lo) {
    __nv_bfloat162 h = __floats2bfloat162_rn(vx, vy);
    hi = *reinterpret_cast<uint32_t*>(&h);
    float rx = vx - __bfloat162float(h.x);
    float ry = vy - __bfloat162float(h.y);
    __nv_bfloat162 l2 = __floats2bfloat162_rn(rx, ry);
    lo = *reinterpret_cast<uint32_t*>(&l2);
}

// SMEM tile geometry: 64 rows x 64 bf16, padded to 72 bf16 (144 B) per row.
// 144 B row stride => ldmatrix's 8 row-pointers land on disjoint bank quads.
#define SKB 144
#define TILE_BYTES (64 * SKB)   // 9216

// ---------------------------------------------------------------------------
// Kernel 1: QKV projection on tensor pipe.
// out[m][n] = sum_c x[m][c] * W[c][n], 3-term bf16 split.
// grid = (M_TOT/64, 3), block = 128 (4 warps, 16 output rows each).
// ---------------------------------------------------------------------------
__global__ __launch_bounds__(128) void qkv_mma_kernel(
    const float* __restrict__ x,
    const float* __restrict__ Wq,
    const float* __restrict__ Wk,
    const float* __restrict__ Wv)
{
    __shared__ __align__(16) char sm[4 * TILE_BYTES];
    // XHI 0 | XLO 9216 | WHI 18432 | WLO 27648

    const float* W = (blockIdx.y == 0) ? Wq : (blockIdx.y == 1) ? Wk : Wv;
    float* out     = (blockIdx.y == 0) ? g_Q : (blockIdx.y == 1) ? g_K : g_V;

    const int tid  = threadIdx.x;
    const int wid  = tid >> 5;
    const int lane = tid & 31;
    const int m0g  = blockIdx.x * 64;
    const uint32_t smb = smem_to_u32(sm);

    float o[8][4];
#pragma unroll
    for (int nt = 0; nt < 8; nt++)
#pragma unroll
        for (int e = 0; e < 4; e++) o[nt][e] = 0.0f;

    // ldmatrix lane address components
    const int a_row  = wid * 16 + (lane & 7) + ((lane >> 3) & 1) * 8;  // A frags
    const int a_colb = (lane >> 4) * 8;
    const int g      = lane >> 3;
    const int t_row  = (lane & 7) + (g & 1) * 8;   // trans B frags (row in k)
    const int t_colb = (g >> 1) * 8;               // (col in n)

    for (int k0 = 0; k0 < C; k0 += 64) {
        // stage x tile [64m x 64k] and W tile [64k x 64n], hi/lo
#pragma unroll
        for (int i = 0; i < 16; i++) {
            int id = tid + i * 128;            // 0..2047 float2 pairs
            int r = id >> 5, c = id & 31;
            float2 xv = *(const float2*)&x[(size_t)(m0g + r) * C + k0 + c * 2];
            uint32_t hi, lo; cvt_hilo(xv.x, xv.y, hi, lo);
            *(uint32_t*)(sm + 0          + r * SKB + c * 4) = hi;
            *(uint32_t*)(sm + TILE_BYTES + r * SKB + c * 4) = lo;
            float2 wv = *(const float2*)&W[(size_t)(k0 + r) * H + c * 2];
            cvt_hilo(wv.x, wv.y, hi, lo);
            *(uint32_t*)(sm + 2 * TILE_BYTES + r * SKB + c * 4) = hi;
            *(uint32_t*)(sm + 3 * TILE_BYTES + r * SKB + c * 4) = lo;
        }
        __syncthreads();

        // A fragments for this k-tile (4 k-steps of 16)
        uint32_t axh[4][4], axl[4][4];
#pragma unroll
        for (int k = 0; k < 4; k++) {
            uint32_t ad = a_row * SKB + (k * 16 + a_colb) * 2;
            ldsm_x4(axh[k], smb + 0          + ad);
            ldsm_x4(axl[k], smb + TILE_BYTES + ad);
        }

#pragma unroll
        for (int np = 0; np < 4; np++) {       // n-tile pairs (16 cols)
#pragma unroll
            for (int k = 0; k < 4; k++) {
                uint32_t bh[4], bl[4];
                uint32_t ad = (k * 16 + t_row) * SKB + (np * 16 + t_colb) * 2;
                ldsm_x4_t(bh, smb + 2 * TILE_BYTES + ad);
                ldsm_x4_t(bl, smb + 3 * TILE_BYTES + ad);
                mma16816(o[2 * np],     axh[k], bh);
                mma16816(o[2 * np + 1], axh[k], bh + 2);
                mma16816(o[2 * np],     axh[k], bl);
                mma16816(o[2 * np + 1], axh[k], bl + 2);
                mma16816(o[2 * np],     axl[k], bh);
                mma16816(o[2 * np + 1], axl[k], bh + 2);
            }
        }
        __syncthreads();
    }

    // epilogue: rows r0, r0+8; cols nt*8 + (lane&3)*2
    const int r0 = m0g + wid * 16 + (lane >> 2);
#pragma unroll
    for (int nt = 0; nt < 8; nt++) {
        int c = nt * 8 + (lane & 3) * 2;
        *(float2*)&out[(size_t)r0 * H + c]       = make_float2(o[nt][0], o[nt][1]);
        *(float2*)&out[(size_t)(r0 + 8) * H + c] = make_float2(o[nt][2], o[nt][3]);
    }
}

// ---------------------------------------------------------------------------
// Kernel 2: split-K causal flash attention on tensor pipe.
// grid = (T/64, NSPLIT, BATCH), block = 128 (4 warps x 16 queries).
// S = Q K^T and O += P V via mma.sync bf16 hi/lo 3-term; softmax in registers.
// ---------------------------------------------------------------------------
__global__ __launch_bounds__(128) void flash_mma_kernel()
{
    __shared__ __align__(16) char sm[4 * TILE_BYTES];
    // KHI 0 | KLO 9216 | VHI 18432 | VLO 27648  (Q staged via KHI/KLO first)

    const int b     = blockIdx.z;
    const int split = blockIdx.y;
    const int qt    = blockIdx.x;
    const int tid   = threadIdx.x;
    const int wid   = tid >> 5;
    const int lane  = tid & 31;
    const int q0    = qt * 64;

    const int seg_begin = split * (T / NSPLIT);
    const int seg_end   = min(seg_begin + T / NSPLIT, q0 + 64);

    if (seg_begin >= seg_end) {
        for (int r = tid; r < 64; r += 128) {
            size_t pb = ((size_t)(b * T) + q0 + r) * NSPLIT + split;
            g_m[pb] = -1e30f;
            g_l[pb] = 0.0f;
        }
        return;
    }

    const uint32_t smb = smem_to_u32(sm);

    // ---- stage Q (reusing K buffers), extract per-warp A fragments ----
    {
        const float* Qg = g_Q + (size_t)(b * T + q0) * H;
#pragma unroll
        for (int i = 0; i < 16; i++) {
            int id = tid + i * 128;
            int r = id >> 5, c = id & 31;
            float2 v = *(const float2*)&Qg[r * H + c * 2];
            uint32_t hi, lo; cvt_hilo(v.x, v.y, hi, lo);
            *(uint32_t*)(sm + 0          + r * SKB + c * 4) = hi;
            *(uint32_t*)(sm + TILE_BYTES + r * SKB + c * 4) = lo;
        }
        __syncthreads();
    }

    const int a_row  = wid * 16 + (lane & 7) + ((lane >> 3) & 1) * 8;
    const int a_colb = (lane >> 4) * 8;
    const int g      = lane >> 3;
    const int nt_row = (lane & 7) + (g >> 1) * 8;  // K (non-trans): row in keys
    const int nt_colb = (g & 1) * 8;               //               col in dims
    const int t_row  = (lane & 7) + (g & 1) * 8;   // V (trans): row in keys
    const int t_colb = (g >> 1) * 8;               //            col in dims

    uint32_t qh[4][4], ql[4][4];
#pragma unroll
    for (int k = 0; k < 4; k++) {
        uint32_t ad = a_row * SKB + (k * 16 + a_colb) * 2;
        ldsm_x4(qh[k], smb + 0          + ad);
        ldsm_x4(ql[k], smb + TILE_BYTES + ad);
    }
    __syncthreads();   // done with Q staging buffers

    float o[8][4];
#pragma unroll
    for (int nt = 0; nt < 8; nt++)
#pragma unroll
        for (int e = 0; e < 4; e++) o[nt][e] = 0.0f;
    float m0 = -1e30f, m1 = -1e30f, l0 = 0.0f, l1 = 0.0f;

    const int row_i0 = wid * 16 + (lane >> 2);   // local query row of c0,c1
    // (row_i1 = row_i0 + 8 for c2,c3)

    for (int kt = seg_begin; kt < seg_end; kt += 64) {
        // ---- stage K,V hi/lo ----
        const float* Kg = g_K + (size_t)(b * T + kt) * H;
        const float* Vg = g_V + (size_t)(b * T + kt) * H;
#pragma unroll
        for (int i = 0; i < 16; i++) {
            int id = tid + i * 128;
            int r = id >> 5, c = id & 31;
            float2 kv = *(const float2*)&Kg[r * H + c * 2];
            uint32_t hi, lo; cvt_hilo(kv.x, kv.y, hi, lo);
            *(uint32_t*)(sm + 0          + r * SKB + c * 4) = hi;
            *(uint32_t*)(sm + TILE_BYTES + r * SKB + c * 4) = lo;
            float2 vv = *(const float2*)&Vg[r * H + c * 2];
            cvt_hilo(vv.x, vv.y, hi, lo);
            *(uint32_t*)(sm + 2 * TILE_BYTES + r * SKB + c * 4) = hi;
            *(uint32_t*)(sm + 3 * TILE_BYTES + r * SKB + c * 4) = lo;
        }
        __syncthreads();

        // ---- S = Q K^T (hi*hi + hi*lo + lo*hi) ----
        float s[8][4];
#pragma unroll
        for (int nt = 0; nt < 8; nt++)
#pragma unroll
            for (int e = 0; e < 4; e++) s[nt][e] = 0.0f;

#pragma unroll
        for (int np = 0; np < 4; np++) {       // key n-tile pairs
#pragma unroll
            for (int k = 0; k < 4; k++) {
                uint32_t bh[4], bl[4];
                uint32_t ad = (np * 16 + nt_row) * SKB + (k * 16 + nt_colb) * 2;
                ldsm_x4(bh, smb + 0          + ad);
                ldsm_x4(bl, smb + TILE_BYTES + ad);
                mma16816(s[2 * np],     qh[k], bh);
                mma16816(s[2 * np + 1], qh[k], bh + 2);
                mma16816(s[2 * np],     qh[k], bl);
                mma16816(s[2 * np + 1], qh[k], bl + 2);
                mma16816(s[2 * np],     ql[k], bh);
                mma16816(s[2 * np + 1], ql[k], bh + 2);
            }
        }

        // ---- online softmax ----
        const bool diag = (kt == q0);          // only tile needing a mask
        float mn0 = -1e30f, mn1 = -1e30f;
#pragma unroll
        for (int nt = 0; nt < 8; nt++) {
#pragma unroll
            for (int e = 0; e < 4; e++) {
                float v = s[nt][e] * 0.125f;   // 1/sqrt(64)
                if (diag) {
                    int j = nt * 8 + (lane & 3) * 2 + (e & 1);
                    int i = row_i0 + (e >> 1) * 8;
                    if (j > i) v = -INFINITY;
                }
                s[nt][e] = v;
            }
            mn0 = fmaxf(mn0, fmaxf(s[nt][0], s[nt][1]));
            mn1 = fmaxf(mn1, fmaxf(s[nt][2], s[nt][3]));
        }
        mn0 = fmaxf(mn0, __shfl_xor_sync(0xFFFFFFFFu, mn0, 1));
        mn0 = fmaxf(mn0, __shfl_xor_sync(0xFFFFFFFFu, mn0, 2));
        mn1 = fmaxf(mn1, __shfl_xor_sync(0xFFFFFFFFu, mn1, 1));
        mn1 = fmaxf(mn1, __shfl_xor_sync(0xFFFFFFFFu, mn1, 2));

        float mnew0 = fmaxf(m0, mn0), mnew1 = fmaxf(m1, mn1);
        float a0 = __expf(m0 - mnew0), a1 = __expf(m1 - mnew1);
        m0 = mnew0; m1 = mnew1;

        float ls0 = 0.0f, ls1 = 0.0f;
        uint32_t aPh[4][4], aPl[4][4];
#pragma unroll
        for (int nt = 0; nt < 8; nt++) {
            float p0 = __expf(s[nt][0] - mnew0);
            float p1 = __expf(s[nt][1] - mnew0);
            float p2 = __expf(s[nt][2] - mnew1);
            float p3 = __expf(s[nt][3] - mnew1);
            ls0 += p0 + p1;
            ls1 += p2 + p3;
            int t = nt >> 1, h = nt & 1;       // k-step t, which half of k16
            cvt_hilo(p0, p1, aPh[t][h * 2 + 0], aPl[t][h * 2 + 0]);
            cvt_hilo(p2, p3, aPh[t][h * 2 + 1], aPl[t][h * 2 + 1]);
            o[nt][0] *= a0; o[nt][1] *= a0;
            o[nt][2] *= a1; o[nt][3] *= a1;
        }
        ls0 += __shfl_xor_sync(0xFFFFFFFFu, ls0, 1);
        ls0 += __shfl_xor_sync(0xFFFFFFFFu, ls0, 2);
        ls1 += __shfl_xor_sync(0xFFFFFFFFu, ls1, 1);
        ls1 += __shfl_xor_sync(0xFFFFFFFFu, ls1, 2);
        l0 = l0 * a0 + ls0;
        l1 = l1 * a1 + ls1;

        // ---- O += P V (hi*hi + hi*lo + lo*hi) ----
#pragma unroll
        for (int dp = 0; dp < 4; dp++) {       // dim n-tile pairs
#pragma unroll
            for (int k = 0; k < 4; k++) {      // k-steps over keys
                uint32_t bh[4], bl[4];
                uint32_t ad = (k * 16 + t_row) * SKB + (dp * 16 + t_colb) * 2;
                ldsm_x4_t(bh, smb + 2 * TILE_BYTES + ad);
                ldsm_x4_t(bl, smb + 3 * TILE_BYTES + ad);
                mma16816(o[2 * dp],     aPh[k], bh);
                mma16816(o[2 * dp + 1], aPh[k], bh + 2);
                mma16816(o[2 * dp],     aPh[k], bl);
                mma16816(o[2 * dp + 1], aPh[k], bl + 2);
                mma16816(o[2 * dp],     aPl[k], bh);
                mma16816(o[2 * dp + 1], aPl[k], bh + 2);
            }
        }
        __syncthreads();   // protect smem before next staging
    }

    // ---- write split partials ----
    const int r0g = q0 + row_i0;
    const size_t pb0 = ((size_t)(b * T) + r0g) * NSPLIT + split;
    const size_t pb1 = ((size_t)(b * T) + r0g + 8) * NSPLIT + split;
#pragma unroll
    for (int nt = 0; nt < 8; nt++) {
        int c = nt * 8 + (lane & 3) * 2;
        *(float2*)&g_acc[pb0 * H + c] = make_float2(o[nt][0], o[nt][1]);
        *(float2*)&g_acc[pb1 * H + c] = make_float2(o[nt][2], o[nt][3]);
    }
    if ((lane & 3) == 0) {
        g_m[pb0] = m0; g_l[pb0] = l0;
        g_m[pb1] = m1; g_l[pb1] = l1;
    }
}

// ---------------------------------------------------------------------------
// Kernel 3: combine split-K partials.
// ---------------------------------------------------------------------------
__global__ __launch_bounds__(256) void combine_kernel(float* __restrict__ out)
{
    int idx   = blockIdx.x * 256 + threadIdx.x;
    int d     = idx & (H - 1);
    int query = idx >> 6;

    float mv[NSPLIT];
    float M = -1e30f;
#pragma unroll
    for (int i = 0; i < NSPLIT; i++) {
        mv[i] = g_m[query * NSPLIT + i];
        M = fmaxf(M, mv[i]);
    }

    float L = 0.0f, o = 0.0f;
#pragma unroll
    for (int i = 0; i < NSPLIT; i++) {
        float w = __expf(mv[i] - M);           // empty split: exp(-1e30-M)=0
        L += g_l[query * NSPLIT + i] * w;
        o += g_acc[((size_t)query * NSPLIT + i) * H + d] * w;
    }
    out[idx] = o / L;
}

// ---------------------------------------------------------------------------
extern "C" void kernel_launch(void* const* d_in, const int* in_sizes, int n_in,
                              void* d_out, int out_size)
{
    const float* x  = (const float*)d_in[0];
    const float* Wq = (const float*)d_in[1];
    const float* Wk = (const float*)d_in[2];
    const float* Wv = (const float*)d_in[3];
    float* out = (float*)d_out;

    qkv_mma_kernel<<<dim3(M_TOT / 64, 3), 128>>>(x, Wq, Wk, Wv);
    flash_mma_kernel<<<dim3(T / 64, NSPLIT, BATCH), 128>>>();
    combine_kernel<<<(M_TOT * H) / 256, 256>>>(out);
}